// round 10
// baseline (speedup 1.0000x reference)
#include <cuda_runtime.h>
#include <cstdint>
#include <cstddef>

// Problem constants
#define NN 32768
#define KK 8192
#define DD 64

// Output layout (tuple order, flattened)
#define OFF_CB  268435456ULL
#define OFF_CS  268959744ULL
#define OFF_EMA 268967936ULL
#define OFF_EMB 269492224ULL

#define DECAY 0.99f
#define OMD   0.01f
#define EPSV  1e-5f
#define KEPS  0.08192f   // K * EPS

// Scratch (device globals; no allocations allowed)
__device__ int   g_idx[NN];
__device__ float g_e2[KK];
__device__ float g_cnt[KK];
__device__ float g_dw[KK * DD];
__device__ float g_n;

// ===========================================================================
// helpers (sm_80-era PTX only: safe for the plain sm_103 ptxas target)
// ===========================================================================
static __device__ __forceinline__ uint32_t smem_u32(const void* p) {
    uint32_t a;
    asm("{ .reg .u64 t; cvta.to.shared.u64 t, %1; cvt.u32.u64 %0, t; }"
        : "=r"(a) : "l"(p));
    return a;
}

#define CP_ASYNC16(dst, src) \
    asm volatile("cp.async.cg.shared.global [%0], [%1], 16;" \
                 :: "r"(dst), "l"(src) : "memory")
#define CP_COMMIT() asm volatile("cp.async.commit_group;" ::: "memory")
#define CP_WAIT0()  asm volatile("cp.async.wait_group 0;"  ::: "memory")

// m16n8k8 row.col tf32 MMA, D += A*B (C aliases D)
static __device__ __forceinline__ void mma_tf32(float* d, const uint32_t* a,
                                                const uint32_t* b) {
    asm volatile(
        "mma.sync.aligned.m16n8k8.row.col.f32.tf32.tf32.f32 "
        "{%0,%1,%2,%3}, {%4,%5,%6,%7}, {%8,%9}, {%0,%1,%2,%3};"
        : "+f"(d[0]), "+f"(d[1]), "+f"(d[2]), "+f"(d[3])
        : "r"(a[0]), "r"(a[1]), "r"(a[2]), "r"(a[3]), "r"(b[0]), "r"(b[1]));
}

// exact hi split: keep top 10 explicit mantissa bits (tf32-representable)
#define TF32_MASK 0xFFFFE000u
static __device__ __forceinline__ uint32_t hi_bits(float v) {
    return __float_as_uint(v) & TF32_MASK;
}
static __device__ __forceinline__ uint32_t lo_bits(float v, uint32_t h) {
    return __float_as_uint(v - __uint_as_float(h)) & TF32_MASK;
}

// ===========================================================================
// 0) zero scratch
// ===========================================================================
__global__ void zero_scratch_kernel() {
    int i = blockIdx.x * 256 + threadIdx.x;
    if (i < KK * DD) g_dw[i] = 0.0f;
    if (i < KK)      g_cnt[i] = 0.0f;
}

// ===========================================================================
// 1) codebook squared norms
// ===========================================================================
__global__ void e2_kernel(const float* __restrict__ e) {
    int k = blockIdx.x * 256 + threadIdx.x;
    const float4* p = reinterpret_cast<const float4*>(e + (size_t)k * DD);
    float s = 0.0f;
#pragma unroll
    for (int i = 0; i < 16; ++i) {
        float4 v = p[i];
        s += v.x * v.x + v.y * v.y + v.z * v.z + v.w * v.w;
    }
    g_e2[k] = s;
}

// ===========================================================================
// 2) Fused tensor-core argmin + encodings + scatter.
//    CTA = 256 threads = 8 warps; 32 rows per CTA -> 1024 CTAs, 2 CTAs/SM
//    (fine granularity kills wave quantization; 4 warps/SMSP hide HMMA rt).
//    Warp w covers n-columns [w*16, w*16+16) of each 128-col tile.
//    3-term tf32 split (validated bit-identical results since round 4).
//    The one-hot zero stripe streams inside the tile loop; the 1.0 per row
//    and the dw/count scatter run in the CTA tail.
// ===========================================================================
#define RPC  32                       // rows per CTA
#define SP   68                       // smem row stride in floats (64 + 4 pad)
#define SPB  (SP * 4)                 // 272 bytes
#define XPLANE (RPC * SPB)            // 8704 bytes per x plane
#define EBUF   (128 * SPB)            // 34816 bytes per e-tile buffer
#define X_HI 0
#define X_LO XPLANE
#define EB0  (2 * XPLANE)
#define EB1  (EB0 + EBUF)
#define CAND_D (EB0 + 2 * EBUF)           // [8][32] float
#define CAND_I (CAND_D + 8 * RPC * 4)     // [8][32] int
#define WIN_OFF (CAND_I + 8 * RPC * 4)    // [32] int
#define ARG_SMEM (WIN_OFF + RPC * 4)

__global__ __launch_bounds__(256, 2)
void argmin_mma_kernel(const float* __restrict__ x, const float* __restrict__ e,
                       float* __restrict__ out) {
    extern __shared__ char sm[];
    const uint32_t sb = smem_u32(sm);
    const int tid = threadIdx.x;
    const int wid = tid >> 5;         // warp = n-column block (0..7)
    const int lane = tid & 31;
    const int g = lane >> 2;          // group id (0..7)
    const int r = lane & 3;           // thread-in-group (0..3)
    const int row0 = blockIdx.x * RPC;
    const int Cn = wid * 16;          // warp's n-offset within the 128 tile

    float* cand_d = reinterpret_cast<float*>(sm + CAND_D);
    int*   cand_i = reinterpret_cast<int*>(sm + CAND_I);
    int*   win    = reinterpret_cast<int*>(sm + WIN_OFF);

    // ---- kick off e tile 0 prefetch (overlaps x staging) ----
    {
        const char* src = reinterpret_cast<const char*>(e);
#pragma unroll
        for (int i = 0; i < 8; ++i) {
            int ch = tid + 256 * i;
            int n = ch >> 4, kq = ch & 15;
            CP_ASYNC16(sb + EB0 + n * SPB + kq * 16, src + ch * 16);
        }
    }
    CP_COMMIT();

    // ---- stage x tile pre-split into X_HI / X_LO planes (512 float4s) ----
    {
        const float4* xg = reinterpret_cast<const float4*>(x + (size_t)row0 * DD);
#pragma unroll
        for (int i = 0; i < 2; ++i) {
            int ch = tid + 256 * i;            // 0..511
            int row = ch >> 4, q = ch & 15;
            float4 v = xg[ch];
            uint32_t hx = hi_bits(v.x), hy = hi_bits(v.y);
            uint32_t hz = hi_bits(v.z), hw = hi_bits(v.w);
            uint4 hv = make_uint4(hx, hy, hz, hw);
            uint4 lv = make_uint4(lo_bits(v.x, hx), lo_bits(v.y, hy),
                                  lo_bits(v.z, hz), lo_bits(v.w, hw));
            *reinterpret_cast<uint4*>(sm + X_HI + row * SPB + q * 16) = hv;
            *reinterpret_cast<uint4*>(sm + X_LO + row * SPB + q * 16) = lv;
        }
    }
    CP_WAIT0();
    __syncthreads();

    float best[4];
    int   bidx[4];
#pragma unroll
    for (int s = 0; s < 4; ++s) { best[s] = 3.402823466e38f; bidx[s] = 0; }

    // encodings base for this CTA (float4 granularity; row stride 2048 f4)
    float4* enc = reinterpret_cast<float4*>(out) + (size_t)row0 * 2048;
    const float4 fz = make_float4(0.0f, 0.0f, 0.0f, 0.0f);

    const int NTILES = KK / 128;   // 64
    for (int t = 0; t < NTILES; ++t) {
        const char* bufc = sm + (((t & 1) == 0) ? EB0 : EB1);

        // prefetch tile t+1 into the other buffer
        if (t + 1 < NTILES) {
            const char* src = reinterpret_cast<const char*>(e + (size_t)(t + 1) * 128 * DD);
            const uint32_t bufn = sb + (((t & 1) == 0) ? EB1 : EB0);
#pragma unroll
            for (int i = 0; i < 8; ++i) {
                int ch = tid + 256 * i;
                int n = ch >> 4, kq = ch & 15;
                CP_ASYNC16(bufn + n * SPB + kq * 16, src + ch * 16);
            }
        }
        CP_COMMIT();

        // ---- stream the zero stripe: rows [0,32) x f4-cols [t*32,t*32+32) ----
        {
            float4* zb = enc + t * 32;
#pragma unroll
            for (int j = 0; j < 4; ++j) {
                int i = tid + 256 * j;         // 0..1023
                int row = i >> 5, c4 = i & 31;
                __stcs(&zb[(size_t)row * 2048 + c4], fz);
            }
        }

        // ---- compute: D[2][2][4], k=64 in 8 steps, 3 tf32 terms ----
        float D[2][2][4];
#pragma unroll
        for (int mf = 0; mf < 2; ++mf)
#pragma unroll
            for (int nb = 0; nb < 2; ++nb)
#pragma unroll
                for (int j = 0; j < 4; ++j) D[mf][nb][j] = 0.0f;

#pragma unroll
        for (int ks = 0; ks < 8; ++ks) {
            // A fragments for this ks (pre-split planes, conflict-free LDS)
            uint32_t ahi[2][4], alo[2][4];
#pragma unroll
            for (int mf = 0; mf < 2; ++mf) {
#pragma unroll
                for (int j = 0; j < 4; ++j) {
                    int row = mf * 16 + g + ((j & 1) ? 8 : 0);
                    int col = ks * 8 + r + ((j & 2) ? 4 : 0);
                    ahi[mf][j] = *reinterpret_cast<const uint32_t*>(
                        sm + X_HI + row * SPB + col * 4);
                    alo[mf][j] = *reinterpret_cast<const uint32_t*>(
                        sm + X_LO + row * SPB + col * 4);
                }
            }
            // B fragments for the warp's 2 n-blocks (raw f32 -> mask split)
            uint32_t bhi[2][2], blo[2][2];
#pragma unroll
            for (int nb = 0; nb < 2; ++nb) {
                const char* np = bufc + (size_t)(Cn + nb * 8 + g) * SPB;
                float v0 = *reinterpret_cast<const float*>(np + (ks * 8 + r) * 4);
                float v1 = *reinterpret_cast<const float*>(np + (ks * 8 + r + 4) * 4);
                bhi[nb][0] = hi_bits(v0);
                bhi[nb][1] = hi_bits(v1);
                blo[nb][0] = lo_bits(v0, bhi[nb][0]);
                blo[nb][1] = lo_bits(v1, bhi[nb][1]);
            }
            // 3 term-passes over 4 independent accumulators
#pragma unroll
            for (int nb = 0; nb < 2; ++nb) {
                mma_tf32(D[0][nb], ahi[0], bhi[nb]);
                mma_tf32(D[1][nb], ahi[1], bhi[nb]);
            }
#pragma unroll
            for (int nb = 0; nb < 2; ++nb) {
                mma_tf32(D[0][nb], alo[0], bhi[nb]);
                mma_tf32(D[1][nb], alo[1], bhi[nb]);
            }
#pragma unroll
            for (int nb = 0; nb < 2; ++nb) {
                mma_tf32(D[0][nb], ahi[0], blo[nb]);
                mma_tf32(D[1][nb], ahi[1], blo[nb]);
            }
        }

        // ---- epilogue: distances + running argmin ----
        // frag c-layout: c0(row', col 2r), c1(row', col 2r+1),
        //                c2(row'+8, col 2r), c3(row'+8, col 2r+1); row'=mf*16+g
#pragma unroll
        for (int nb = 0; nb < 2; ++nb) {
            int col = t * 128 + Cn + nb * 8 + r * 2;
            float2 q = *reinterpret_cast<const float2*>(&g_e2[col]);
#pragma unroll
            for (int mf = 0; mf < 2; ++mf) {
                float d0 = fmaf(-2.0f, D[mf][nb][0], q.x);
                float d1 = fmaf(-2.0f, D[mf][nb][1], q.y);
                float d2 = fmaf(-2.0f, D[mf][nb][2], q.x);
                float d3 = fmaf(-2.0f, D[mf][nb][3], q.y);
                int s0 = mf * 2, s1 = mf * 2 + 1;   // rows mf*16+g, mf*16+g+8
                if (d0 < best[s0]) { best[s0] = d0; bidx[s0] = col; }
                if (d1 < best[s0]) { best[s0] = d1; bidx[s0] = col + 1; }
                if (d2 < best[s1]) { best[s1] = d2; bidx[s1] = col; }
                if (d3 < best[s1]) { best[s1] = d3; bidx[s1] = col + 1; }
            }
        }

        CP_WAIT0();
        __syncthreads();
    }

    // ---- reduce across the 4 lanes of each quad (same rows, diff cols) ----
#pragma unroll
    for (int m = 1; m <= 2; m <<= 1) {
#pragma unroll
        for (int s = 0; s < 4; ++s) {
            float ob = __shfl_xor_sync(0xffffffffu, best[s], m);
            int   oi = __shfl_xor_sync(0xffffffffu, bidx[s], m);
            if (ob < best[s] || (ob == best[s] && oi < bidx[s])) {
                best[s] = ob; bidx[s] = oi;
            }
        }
    }
    if (r == 0) {
        // rows owned: s0: g, s1: g+8, s2: g+16, s3: g+24
#pragma unroll
        for (int s = 0; s < 4; ++s) {
            int row = g + s * 8;
            cand_d[wid * RPC + row] = best[s];
            cand_i[wid * RPC + row] = bidx[s];
        }
    }
    __syncthreads();   // also orders zero stores before the 1.0 stores
    if (tid < RPC) {
        float bd = cand_d[tid];
        int   bi = cand_i[tid];
#pragma unroll
        for (int w = 1; w < 8; ++w) {
            float d = cand_d[w * RPC + tid];
            int   i = cand_i[w * RPC + tid];
            if (d < bd || (d == bd && i < bi)) { bd = d; bi = i; }
        }
        win[tid] = bi;
        g_idx[row0 + tid] = bi;
        out[(size_t)(row0 + tid) * KK + bi] = 1.0f;   // the one-hot 1
    }
    __syncthreads();

    // ---- fused dw/count scatter for this CTA's 32 rows ----
    for (int i = tid; i < RPC * DD; i += 256) {
        int n = i >> 6, d = i & 63;
        int k = win[n];
        atomicAdd(&g_dw[(size_t)k * DD + d], x[(size_t)(row0 + n) * DD + d]);
        if (d == 0) atomicAdd(&g_cnt[k], 1.0f);
    }
}

// ===========================================================================
// 3) n = sum(cluster_size_pre)
// ===========================================================================
__global__ void reduce_n_kernel(const float* __restrict__ ema_cs) {
    __shared__ float sh[1024];
    int t = threadIdx.x;
    float s = 0.0f;
    for (int k = t; k < KK; k += 1024) {
        float cs = __fadd_rn(__fmul_rn(ema_cs[k], DECAY), __fmul_rn(OMD, g_cnt[k]));
        s += cs;
    }
    sh[t] = s;
    __syncthreads();
    for (int m = 512; m > 0; m >>= 1) {
        if (t < m) sh[t] += sh[t + m];
        __syncthreads();
    }
    if (t == 0) g_n = sh[0];
}

// ===========================================================================
// 4) finalize
// ===========================================================================
__global__ void finalize_kernel(const float* __restrict__ emb_w,
                                const float* __restrict__ ema_w,
                                const float* __restrict__ ema_cs,
                                float* __restrict__ out) {
    int gid = blockIdx.x * 256 + threadIdx.x;
    int k = gid >> 6, d = gid & 63;
    float nsum = g_n;
    float cs  = __fadd_rn(__fmul_rn(ema_cs[k], DECAY), __fmul_rn(OMD, g_cnt[k]));
    float csn = __fmul_rn(__fdiv_rn(__fadd_rn(cs, EPSV), __fadd_rn(nsum, KEPS)), nsum);
    float ema_new = __fadd_rn(__fmul_rn(ema_w[gid], DECAY), __fmul_rn(OMD, g_dw[gid]));
    out[OFF_CB  + gid] = emb_w[gid];
    out[OFF_EMA + gid] = ema_new;
    out[OFF_EMB + gid] = __fdiv_rn(ema_new, csn);
    if (d == 0) out[OFF_CS + k] = csn;
}

// ===========================================================================
extern "C" void kernel_launch(void* const* d_in, const int* in_sizes, int n_in,
                              void* d_out, int out_size) {
    const float* x       = (const float*)d_in[0];
    const float* emb_w   = (const float*)d_in[1];
    const float* ema_w   = (const float*)d_in[2];
    const float* ema_cs  = (const float*)d_in[3];
    float* out = (float*)d_out;

    cudaFuncSetAttribute(argmin_mma_kernel,
                         cudaFuncAttributeMaxDynamicSharedMemorySize, ARG_SMEM);

    zero_scratch_kernel<<<2048, 256>>>();
    e2_kernel<<<KK / 256, 256>>>(emb_w);
    argmin_mma_kernel<<<NN / RPC, 256, ARG_SMEM>>>(x, emb_w, out);
    reduce_n_kernel<<<1, 1024>>>(ema_cs);
    finalize_kernel<<<(KK * DD) / 256, 256>>>(emb_w, ema_w, ema_cs, out);
}